// round 17
// baseline (speedup 1.0000x reference)
#include <cuda_runtime.h>
#include <cuda_fp16.h>
#include <cstdint>

#define E_N 100000
#define R_N 64
#define I_N 256
#define O_N 256
#define TILE_M 336
#define N_TILES ((E_N + TILE_M - 1) / TILE_M)   // 298 (single wave, 2 CTAs/SM)

// main-kernel smem: A hi/lo planes + xs array; init-only s_w overlays A.
#define A_STRIDE 144                   // %128==16 -> conflict-free LDSM
#define A_BUF    (TILE_M * A_STRIDE)   // 48384
#define SM_XS    (2 * A_BUF)           // 96768: 336 floats
#define SM_TOT   (SM_XS + TILE_M * 4)  // 98112 -> 2 CTAs/SM

__device__ float g_wpart[16 * R_N * O_N];
__device__ float g_wsum[R_N * O_N];

// ---------------------------------------------------------------------------
// Kernel 1: W partial sums (1024 blocks = (r, i-16th)).
// ---------------------------------------------------------------------------
__global__ __launch_bounds__(256, 8)
void wsum_part_kernel(const float* __restrict__ W) {
    const int r = blockIdx.x & 63;
    const int part = blockIdx.x >> 6;
    const int o = threadIdx.x;
    const float* base = W + ((size_t)(r * I_N + part * 16)) * O_N + o;
    float s = 0.f;
#pragma unroll
    for (int i = 0; i < 16; ++i) s += base[(size_t)i * O_N];
    g_wpart[(part * R_N + r) * O_N + o] = s;
}

// ---------------------------------------------------------------------------
// Kernel 2: collapse W partials -> g_wsum.
// ---------------------------------------------------------------------------
__global__ void wsum_final_kernel() {
    const int r = blockIdx.x, o = threadIdx.x;
    float s = 0.f;
#pragma unroll
    for (int p = 0; p < 16; ++p) s += g_wpart[(p * R_N + r) * O_N + o];
    g_wsum[r * O_N + o] = s;
}

// ---------------------------------------------------------------------------
// helpers
// ---------------------------------------------------------------------------
static __device__ __forceinline__ void mma16816(float* acc, const uint32_t* a,
                                                uint32_t b0, uint32_t b1) {
    asm volatile(
        "mma.sync.aligned.m16n8k16.row.col.f32.f16.f16.f32 "
        "{%0,%1,%2,%3}, {%4,%5,%6,%7}, {%8,%9}, {%0,%1,%2,%3};"
        : "+f"(acc[0]), "+f"(acc[1]), "+f"(acc[2]), "+f"(acc[3])
        : "r"(a[0]), "r"(a[1]), "r"(a[2]), "r"(a[3]), "r"(b0), "r"(b1));
}
static __device__ __forceinline__ void ldsm4(uint32_t* r, uint32_t saddr) {
    asm volatile("ldmatrix.sync.aligned.m8n8.x4.shared.b16 {%0,%1,%2,%3}, [%4];"
                 : "=r"(r[0]), "=r"(r[1]), "=r"(r[2]), "=r"(r[3]) : "r"(saddr));
}
static __device__ __forceinline__ uint32_t pack2(__half a, __half b) {
    __half2 h; h.x = a; h.y = b;
    return *(uint32_t*)&h;
}
static __device__ __forceinline__ void split16(float v, __half& hi, __half& lo) {
    hi = __float2half_rn(v);
    lo = __float2half_rn(v - __half2float(hi));
}
// FMA-pipe reciprocal (no MUFU): magic seed + 2 Newton iterations
static __device__ __forceinline__ float frcp(float y) {
    float r = __uint_as_float(0x7EF311C3u - __float_as_uint(y));
    r = r * __fmaf_rn(-y, r, 2.0f);
    r = r * __fmaf_rn(-y, r, 2.0f);
    return r;
}

// ---------------------------------------------------------------------------
// Kernel 3: ONE tile per CTA (grid=298, 2 CTAs/SM). Phases:
//   B-frag init -> x streaming row-sums (8 warps x 2 rows/iter x 21 iters)
//   -> barrier -> prep (cs recip + fp16 split -> A smem) -> barrier
//   -> MMA + store.
// ---------------------------------------------------------------------------
__global__ __launch_bounds__(256, 2)
void rgcn_hmma_kernel(const float* __restrict__ x,
                      const float* __restrict__ cs,
                      float* __restrict__ out) {
    extern __shared__ __align__(16) char sm[];
    const uint32_t sbase = (uint32_t)__cvta_generic_to_shared(sm);
    const int t = threadIdx.x;
    const int warp = t >> 5, lane = t & 31;

    // ---- init: stage Wsum in smem (overlays A planes), extract B frags ----
    float* s_w = (float*)sm;
#pragma unroll 4
    for (int i = 0; i < 64; ++i) {
        int idx = i * 256 + t;
        s_w[idx] = g_wsum[idx];
    }
    __syncthreads();

    uint32_t bh[4][4][2], bl[4][4][2];
    {
        const int n = warp * 32 + (lane >> 2);
#pragma unroll
        for (int nt = 0; nt < 4; ++nt)
#pragma unroll
            for (int ks = 0; ks < 4; ++ks) {
                int kb = ks * 16 + 2 * (lane & 3);
                int nn = n + nt * 8;
                float w00 = s_w[kb * 256 + nn];
                float w01 = s_w[(kb + 1) * 256 + nn];
                float w10 = s_w[(kb + 8) * 256 + nn];
                float w11 = s_w[(kb + 9) * 256 + nn];
                __half h00, l00, h01, l01, h10, l10, h11, l11;
                split16(w00, h00, l00); split16(w01, h01, l01);
                split16(w10, h10, l10); split16(w11, h11, l11);
                bh[nt][ks][0] = pack2(h00, h01); bh[nt][ks][1] = pack2(h10, h11);
                bl[nt][ks][0] = pack2(l00, l01); bl[nt][ks][1] = pack2(l10, l11);
            }
    }
    __syncthreads();   // s_w dead; A planes + xs writable

    const int ebase = blockIdx.x * TILE_M;
    float* s_xs = (float*)(sm + SM_XS);

    // ========= X PHASE: row sums; 8 warps, 2 rows per warp per iter =========
#pragma unroll 3
    for (int it = 0; it < 21; ++it) {
        const int rowA = it * 16 + warp;         // 0..335 (warp 0..7)
        const int rowB = rowA + 8;
        int eA = ebase + rowA; if (eA > E_N - 1) eA = E_N - 1;
        int eB = ebase + rowB; if (eB > E_N - 1) eB = E_N - 1;
        const float4* xpA = (const float4*)x + (size_t)eA * 64;
        const float4* xpB = (const float4*)x + (size_t)eB * 64;
        float4 a0 = xpA[lane], a1 = xpA[lane + 32];
        float4 b0 = xpB[lane], b1 = xpB[lane + 32];
        float sA = (a0.x + a0.y) + (a0.z + a0.w) + (a1.x + a1.y) + (a1.z + a1.w);
        float sB = (b0.x + b0.y) + (b0.z + b0.w) + (b1.x + b1.y) + (b1.z + b1.w);
#pragma unroll
        for (int d = 16; d; d >>= 1) {
            sA += __shfl_xor_sync(0xffffffffu, sA, d);
            sB += __shfl_xor_sync(0xffffffffu, sB, d);
        }
        if (lane == 0) {
            s_xs[rowA] = sA;
            s_xs[rowB] = sB;
        }
    }
    __syncthreads();   // xs ready

    // ================= PREP: 3 passes of 128 half-row pairs =================
    const int el = t >> 1, kh = t & 1;
    const float4* __restrict__ cs4 = (const float4*)cs;
#pragma unroll
    for (int p = 0; p < 3; ++p) {
        const int row = p * 128 + el;
        if (row < TILE_M) {
            int e = ebase + row;
            if (e > E_N - 1) e = E_N - 1;
            float xs = s_xs[row];
            const float4* cp = cs4 + (size_t)e * 16 + kh * 8;
            uint32_t hw[16], lw[16];
#pragma unroll
            for (int q = 0; q < 8; ++q) {
                float4 c = cp[q];
                float v0 = xs * frcp(c.x);
                float v1 = xs * frcp(c.y);
                float v2 = xs * frcp(c.z);
                float v3 = xs * frcp(c.w);
                __half h0, l0, h1, l1, h2, l2, h3, l3;
                split16(v0, h0, l0); split16(v1, h1, l1);
                split16(v2, h2, l2); split16(v3, h3, l3);
                hw[2 * q] = pack2(h0, h1); hw[2 * q + 1] = pack2(h2, h3);
                lw[2 * q] = pack2(l0, l1); lw[2 * q + 1] = pack2(l2, l3);
            }
            uint32_t off = row * A_STRIDE + kh * 64;
            uint4* dh = (uint4*)(sm + off);
            uint4* dl = (uint4*)(sm + off + A_BUF);
#pragma unroll
            for (int q = 0; q < 4; ++q) {
                dh[q] = make_uint4(hw[4 * q], hw[4 * q + 1], hw[4 * q + 2], hw[4 * q + 3]);
                dl[q] = make_uint4(lw[4 * q], lw[4 * q + 1], lw[4 * q + 2], lw[4 * q + 3]);
            }
        }
    }
    __syncthreads();   // A ready

    // ================= MMA + STORE: 21 x 16-row slabs =======================
    {
        const uint32_t ah_base = sbase;
        const uint32_t al_base = sbase + A_BUF;
        const uint32_t lrow = (lane & 7) + ((lane >> 3) & 1) * 8;
        const uint32_t lcol = (lane >> 4) * 16;
        const int gr = lane >> 2;
        const int col = warp * 32 + (lane & 3) * 2;

#pragma unroll 1
        for (int m0 = 0; m0 < TILE_M; m0 += 16) {
            uint32_t fo = (m0 + lrow) * A_STRIDE + lcol;
            float acc[4][4];
#pragma unroll
            for (int nt = 0; nt < 4; ++nt)
                acc[nt][0] = acc[nt][1] = acc[nt][2] = acc[nt][3] = 0.f;
#pragma unroll
            for (int ks = 0; ks < 4; ++ks) {
                uint32_t ah[4], al[4];
                ldsm4(ah, ah_base + fo + ks * 32);
                ldsm4(al, al_base + fo + ks * 32);
#pragma unroll
                for (int nt = 0; nt < 4; ++nt) {
                    mma16816(acc[nt], ah, bh[nt][ks][0], bh[nt][ks][1]);
                    mma16816(acc[nt], ah, bl[nt][ks][0], bl[nt][ks][1]);
                    mma16816(acc[nt], al, bh[nt][ks][0], bh[nt][ks][1]);
                }
            }
            int e0 = ebase + m0 + gr, e1 = e0 + 8;
            if (e0 < E_N) {
                float* p = out + (size_t)e0 * O_N + col;
#pragma unroll
                for (int nt = 0; nt < 4; ++nt)
                    *(float2*)(p + nt * 8) = make_float2(acc[nt][0], acc[nt][1]);
            }
            if (e1 < E_N) {
                float* p = out + (size_t)e1 * O_N + col;
#pragma unroll
                for (int nt = 0; nt < 4; ++nt)
                    *(float2*)(p + nt * 8) = make_float2(acc[nt][2], acc[nt][3]);
            }
        }
    }
}

// ---------------------------------------------------------------------------
// Inputs: x[E,256] f32, cs[E,64] f32, W[64,256,256] f32, edge_index (unused).
// Output: f32 [E,256].
// ---------------------------------------------------------------------------
extern "C" void kernel_launch(void* const* d_in, const int* in_sizes, int n_in,
                              void* d_out, int out_size) {
    const float* x  = (const float*)d_in[0];
    const float* cs = (const float*)d_in[1];
    const float* W  = (const float*)d_in[2];
    float* out = (float*)d_out;
    (void)in_sizes; (void)n_in; (void)out_size;

    cudaFuncSetAttribute(rgcn_hmma_kernel,
                         cudaFuncAttributeMaxDynamicSharedMemorySize, SM_TOT);

    wsum_part_kernel<<<1024, 256>>>(W);
    wsum_final_kernel<<<R_N, O_N>>>();
    rgcn_hmma_kernel<<<N_TILES, 256, SM_TOT>>>(x, cs, out);
}